// round 3
// baseline (speedup 1.0000x reference)
#include <cuda_runtime.h>

#define BATCH 16
#define NNODE 32
#define DEG 64
#define KNN 8
#define IN_F 128
#define OUT_F 3
#define NPTS 2048   // NNODE*DEG
#define JCOLS 8192  // DEG*IN_F

// ---------- device scratch (no allocations allowed) ----------
__device__ float  g_root[BATCH * NNODE * OUT_F];
__device__ float  g_Wl[IN_F * OUT_F];     // collapsed Wl1@Wl2, layout [f*3+o]
__device__ float  g_ceff[OUT_F * 6];      // collapsed c2w@c1w, layout [p*6+c]
__device__ float  g_beff[OUT_F];          // c2w@c1b + c2b
__device__ float4 g_x[BATCH * NPTS];      // (x0,x1,x2, 0.5*||x||^2)

// ---------- packed f32x2 helpers ----------
__device__ __forceinline__ unsigned long long splat2(float w) {
    unsigned long long r;
    asm("mov.b64 %0, {%1, %1};" : "=l"(r) : "f"(w));
    return r;
}
__device__ __forceinline__ void ffma2(unsigned long long& d,
                                      unsigned long long a,
                                      unsigned long long b) {
    asm("fma.rn.f32x2 %0, %1, %2, %0;" : "+l"(d) : "l"(a), "l"(b));
}

__device__ __forceinline__ float wredsum(float v) {
    #pragma unroll
    for (int o = 16; o > 0; o >>= 1) v += __shfl_xor_sync(0xffffffffu, v, o);
    return v;
}

// ============================================================
// K0: parallel prep. 641 blocks x 128 threads, warp-shuffle reductions.
// ============================================================
__global__ __launch_bounds__(128) void k0_prep(
        const float* __restrict__ t0, const float* __restrict__ t1,
        const float* __restrict__ t2, const float* __restrict__ t3,
        const float* __restrict__ t4, const float* __restrict__ t5,
        const float* __restrict__ Wr0, const float* __restrict__ Wr1,
        const float* __restrict__ Wr2, const float* __restrict__ Wr3,
        const float* __restrict__ Wr4, const float* __restrict__ Wr5,
        const float* __restrict__ Wl1, const float* __restrict__ Wl2,
        const float* __restrict__ c1w, const float* __restrict__ c1b,
        const float* __restrict__ c2w, const float* __restrict__ c2b) {
    const int bid = blockIdx.x;
    const int tid = threadIdx.x;
    const int w   = tid >> 5, lane = tid & 31;
    __shared__ float red[4][3];

    if (bid < 512) {
        const int b = bid >> 5, n = bid & 31;
        float s0 = 0.f, s1 = 0.f, s2 = 0.f;
        for (int idx = tid; idx < 1120; idx += 128) {
            float v; const float* wp;
            if (idx < 96) {
                v = t0[b * 96 + idx];                           wp = Wr0 + idx * 3;
            } else if (idx < 352) {
                int i = idx - 96;
                v = t1[(b * 2  + (n >> 4)) * 256 + i];          wp = Wr1 + i * 3;
            } else if (idx < 608) {
                int i = idx - 352;
                v = t2[(b * 4  + (n >> 3)) * 256 + i];          wp = Wr2 + i * 3;
            } else if (idx < 864) {
                int i = idx - 608;
                v = t3[(b * 8  + (n >> 2)) * 256 + i];          wp = Wr3 + i * 3;
            } else if (idx < 992) {
                int i = idx - 864;
                v = t4[(b * 16 + (n >> 1)) * 128 + i];          wp = Wr4 + i * 3;
            } else {
                int i = idx - 992;
                v = t5[(b * 32 +  n      ) * 128 + i];          wp = Wr5 + i * 3;
            }
            s0 = fmaf(v, wp[0], s0); s1 = fmaf(v, wp[1], s1); s2 = fmaf(v, wp[2], s2);
        }
        s0 = wredsum(s0); s1 = wredsum(s1); s2 = wredsum(s2);
        if (lane == 0) { red[w][0] = s0; red[w][1] = s1; red[w][2] = s2; }
        __syncthreads();
        if (tid < 3)
            g_root[(b * NNODE + n) * 3 + tid] =
                red[0][tid] + red[1][tid] + red[2][tid] + red[3][tid];
    } else if (bid < 640) {
        const int f = bid - 512;
        float s0 = 0.f, s1 = 0.f, s2 = 0.f;
        for (int tt = tid; tt < 1280; tt += 128) {
            float v = Wl1[f * 1280 + tt];
            s0 = fmaf(v, Wl2[tt * 3 + 0], s0);
            s1 = fmaf(v, Wl2[tt * 3 + 1], s1);
            s2 = fmaf(v, Wl2[tt * 3 + 2], s2);
        }
        s0 = wredsum(s0); s1 = wredsum(s1); s2 = wredsum(s2);
        if (lane == 0) { red[w][0] = s0; red[w][1] = s1; red[w][2] = s2; }
        __syncthreads();
        if (tid < 3)
            g_Wl[f * 3 + tid] =
                red[0][tid] + red[1][tid] + red[2][tid] + red[3][tid];
    } else {
        if (tid < 18) {
            int p = tid / 6, c = tid % 6;
            float s = 0.f;
            for (int o = 0; o < 64; o++) s = fmaf(c2w[p * 64 + o], c1w[o * 6 + c], s);
            g_ceff[tid] = s;
        } else if (tid < 21) {
            int p = tid - 18;
            float s = c2b[p];
            for (int o = 0; o < 64; o++) s = fmaf(c2w[p * 64 + o], c1b[o], s);
            g_beff[p] = s;
        }
    }
}

// ============================================================
// K1: x[b, n*64+d, :] = root[b,n,:] + leaky(t5[b,n,:] @ W_branch[n]) @ Wl
// ============================================================
__global__ __launch_bounds__(128) void k1_branch(const float* __restrict__ t5,
                                                 const float* __restrict__ Wb) {
    const int n   = blockIdx.x >> 4;
    const int jt  = blockIdx.x & 15;
    const int j0  = jt * 512;
    const int tid = threadIdx.x;

    __shared__ __align__(16) unsigned long long sa[IN_F * 8];
    __shared__ __align__(16) float sC[16][516];        // pad 516 (16B-aligned rows)
    __shared__ float sWlT[3][128];

    {
        int i = tid;
        #pragma unroll
        for (int p = 0; p < 8; p++) {
            float a0 = t5[((2 * p)     * NNODE + n) * IN_F + i];
            float a1 = t5[((2 * p + 1) * NNODE + n) * IN_F + i];
            sa[i * 8 + p] = ((unsigned long long)__float_as_uint(a1) << 32)
                          | (unsigned long long)__float_as_uint(a0);
        }
        for (int q = tid; q < 384; q += 128)
            sWlT[q >> 7][q & 127] = g_Wl[(q & 127) * 3 + (q >> 7)];
    }
    __syncthreads();

    unsigned long long acc[4][8];
    #pragma unroll
    for (int c = 0; c < 4; c++)
        #pragma unroll
        for (int p = 0; p < 8; p++) acc[c][p] = 0ull;

    const float4* wptr =
        (const float4*)(Wb + (size_t)n * IN_F * JCOLS + j0 + 4 * tid);

    #pragma unroll 4
    for (int i = 0; i < IN_F; i++) {
        float4 w = wptr[(size_t)i * (JCOLS / 4)];
        unsigned long long w0 = splat2(w.x), w1 = splat2(w.y),
                           w2 = splat2(w.z), w3 = splat2(w.w);
        const ulonglong2* sap = (const ulonglong2*)(sa + i * 8);
        #pragma unroll
        for (int q = 0; q < 4; q++) {
            ulonglong2 ap = sap[q];
            ffma2(acc[0][2 * q], ap.x, w0);
            ffma2(acc[1][2 * q], ap.x, w1);
            ffma2(acc[2][2 * q], ap.x, w2);
            ffma2(acc[3][2 * q], ap.x, w3);
            ffma2(acc[0][2 * q + 1], ap.y, w0);
            ffma2(acc[1][2 * q + 1], ap.y, w1);
            ffma2(acc[2][2 * q + 1], ap.y, w2);
            ffma2(acc[3][2 * q + 1], ap.y, w3);
        }
    }

    // leaky -> sC, vectorized over the 4 columns of this thread
    #pragma unroll
    for (int p = 0; p < 8; p++) {
        float lo[4], hi[4];
        #pragma unroll
        for (int c = 0; c < 4; c++) {
            float l = __uint_as_float((unsigned)(acc[c][p] & 0xffffffffu));
            float h = __uint_as_float((unsigned)(acc[c][p] >> 32));
            lo[c] = l >= 0.f ? l : 0.2f * l;
            hi[c] = h >= 0.f ? h : 0.2f * h;
        }
        *(float4*)&sC[2 * p][4 * tid]     = make_float4(lo[0], lo[1], lo[2], lo[3]);
        *(float4*)&sC[2 * p + 1][4 * tid] = make_float4(hi[0], hi[1], hi[2], hi[3]);
    }
    __syncthreads();

    // projection: thread t<64 handles one (d,b); float4 reads
    if (tid < 64) {
        int d = tid >> 4, b = tid & 15;
        const float4* rowv = (const float4*)&sC[b][d * 128];
        const float4* w0v = (const float4*)sWlT[0];
        const float4* w1v = (const float4*)sWlT[1];
        const float4* w2v = (const float4*)sWlT[2];
        float s0 = 0.f, s1 = 0.f, s2 = 0.f;
        #pragma unroll 8
        for (int fq = 0; fq < 32; fq++) {
            float4 cv = rowv[fq];
            float4 a0 = w0v[fq], a1 = w1v[fq], a2 = w2v[fq];
            s0 = fmaf(cv.x, a0.x, fmaf(cv.y, a0.y, fmaf(cv.z, a0.z, fmaf(cv.w, a0.w, s0))));
            s1 = fmaf(cv.x, a1.x, fmaf(cv.y, a1.y, fmaf(cv.z, a1.z, fmaf(cv.w, a1.w, s1))));
            s2 = fmaf(cv.x, a2.x, fmaf(cv.y, a2.y, fmaf(cv.z, a2.z, fmaf(cv.w, a2.w, s2))));
        }
        const float* rp = &g_root[(b * NNODE + n) * 3];
        float x0 = s0 + rp[0], x1 = s1 + rp[1], x2 = s2 + rp[2];
        float hxx = 0.5f * (x0 * x0 + x1 * x1 + x2 * x2);
        int dglob = jt * 4 + d;
        g_x[b * NPTS + n * DEG + dglob] = make_float4(x0, x1, x2, hxx);
    }
}

// ============================================================
// K2: per (b,n): exact top-8 of score = dot - 0.5xxn - 0.5xxm.
// 4 lanes per point each scan a 512-candidate chunk; in-warp merge via
// shfl + bitonic split with (val desc, idx asc) comparator (== lax.top_k
// tie semantics). Then collapsed edge-MLP + max-over-k + bias + leaky.
// ============================================================
__device__ __forceinline__ void topk_insert(float v, int m, float* val, int* idx) {
    val[KNN - 1] = v; idx[KNN - 1] = m;
    #pragma unroll
    for (int s = KNN - 1; s >= 1; s--) {
        if (val[s] > val[s - 1]) {
            float tv = val[s]; val[s] = val[s - 1]; val[s - 1] = tv;
            int   ti = idx[s]; idx[s] = idx[s - 1]; idx[s - 1] = ti;
        } else break;
    }
}

// compare-exchange: keep GT-max (val desc, idx asc) at position i
__device__ __forceinline__ void ce_desc(float& vi, int& ii, float& vj, int& ij) {
    bool sw = (vj > vi) || (vj == vi && ij < ii);
    if (sw) {
        float tv = vi; vi = vj; vj = tv;
        int   ti = ii; ii = ij; ij = ti;
    }
}

__global__ __launch_bounds__(256) void k2_knn(const float* __restrict__ bias,
                                              float* __restrict__ out) {
    const int b    = blockIdx.x >> 5;     // 16 batches x 32 tiles
    const int tile = blockIdx.x & 31;
    const int tid  = threadIdx.x;

    __shared__ float4 sxp[4][513];        // 4 sections, padded -> distinct banks
    __shared__ float  sce[18], sbe[3];
    for (int q = tid; q < NPTS; q += 256)
        sxp[q >> 9][q & 511] = g_x[b * NPTS + q];
    if (tid < 18) sce[tid] = g_ceff[tid];
    if (tid < 3)  sbe[tid] = g_beff[tid];
    __syncthreads();

    const int p = tid >> 2;               // point within tile (0..63)
    const int n = tile * 64 + p;          // point within batch
    const int c = tid & 3;                // scan chunk
    const float4 xn = sxp[n >> 9][n & 511];
    const float nx = xn.x, ny = xn.y, nz = xn.z, negw = -xn.w;

    float val[KNN]; int idx[KNN];
    #pragma unroll
    for (int k = 0; k < KNN; k++) { val[k] = -3.4e38f; idx[k] = 0; }

    const int mbase = c * 512;
    #pragma unroll 1
    for (int m0 = 0; m0 < 512; m0 += 4) {
        float4 xa = sxp[c][m0],     xb = sxp[c][m0 + 1],
               xc = sxp[c][m0 + 2], xd = sxp[c][m0 + 3];
        float p0 = fmaf(nx, xa.x, fmaf(ny, xa.y, fmaf(nz, xa.z, negw - xa.w)));
        float p1 = fmaf(nx, xb.x, fmaf(ny, xb.y, fmaf(nz, xb.z, negw - xb.w)));
        float p2 = fmaf(nx, xc.x, fmaf(ny, xc.y, fmaf(nz, xc.z, negw - xc.w)));
        float p3 = fmaf(nx, xd.x, fmaf(ny, xd.y, fmaf(nz, xd.z, negw - xd.w)));
        float gm = fmaxf(fmaxf(p0, p1), fmaxf(p2, p3));
        if (gm > val[KNN - 1]) {
            if (p0 > val[KNN - 1]) topk_insert(p0, mbase + m0,     val, idx);
            if (p1 > val[KNN - 1]) topk_insert(p1, mbase + m0 + 1, val, idx);
            if (p2 > val[KNN - 1]) topk_insert(p2, mbase + m0 + 2, val, idx);
            if (p3 > val[KNN - 1]) topk_insert(p3, mbase + m0 + 3, val, idx);
        }
    }

    // ---- merge round 1: lanes c in {0,2} absorb lane c+1 ----
    {
        float bv[KNN]; int bi[KNN];
        #pragma unroll
        for (int k = 0; k < KNN; k++) {
            bv[k] = __shfl_down_sync(0xffffffffu, val[k], 1);
            bi[k] = __shfl_down_sync(0xffffffffu, idx[k], 1);
        }
        if ((c & 1) == 0) {
            float mv[KNN]; int mi[KNN];
            #pragma unroll
            for (int i = 0; i < KNN; i++) {
                bool ga = (val[i] > bv[7 - i]) ||
                          (val[i] == bv[7 - i] && idx[i] < bi[7 - i]);
                mv[i] = ga ? val[i] : bv[7 - i];
                mi[i] = ga ? idx[i] : bi[7 - i];
            }
            // bitonic merge (sequence is bitonic) -> fully sorted desc
            ce_desc(mv[0], mi[0], mv[4], mi[4]);
            ce_desc(mv[1], mi[1], mv[5], mi[5]);
            ce_desc(mv[2], mi[2], mv[6], mi[6]);
            ce_desc(mv[3], mi[3], mv[7], mi[7]);
            ce_desc(mv[0], mi[0], mv[2], mi[2]);
            ce_desc(mv[1], mi[1], mv[3], mi[3]);
            ce_desc(mv[4], mi[4], mv[6], mi[6]);
            ce_desc(mv[5], mi[5], mv[7], mi[7]);
            ce_desc(mv[0], mi[0], mv[1], mi[1]);
            ce_desc(mv[2], mi[2], mv[3], mi[3]);
            ce_desc(mv[4], mi[4], mv[5], mi[5]);
            ce_desc(mv[6], mi[6], mv[7], mi[7]);
            #pragma unroll
            for (int k = 0; k < KNN; k++) { val[k] = mv[k]; idx[k] = mi[k]; }
        }
    }
    // ---- merge round 2: lane c==0 absorbs lane c==2 (set only) ----
    {
        float bv[KNN]; int bi[KNN];
        #pragma unroll
        for (int k = 0; k < KNN; k++) {
            bv[k] = __shfl_down_sync(0xffffffffu, val[k], 2);
            bi[k] = __shfl_down_sync(0xffffffffu, idx[k], 2);
        }
        if (c == 0) {
            #pragma unroll
            for (int i = 0; i < KNN; i++) {
                bool ga = (val[i] > bv[7 - i]) ||
                          (val[i] == bv[7 - i] && idx[i] < bi[7 - i]);
                val[i] = ga ? val[i] : bv[7 - i];
                idx[i] = ga ? idx[i] : bi[7 - i];
            }
        }
    }

    if (c == 0) {
        float h0 = -3.4e38f, h1 = -3.4e38f, h2 = -3.4e38f;
        #pragma unroll
        for (int k = 0; k < KNN; k++) {
            int m = idx[k];
            float4 xm = sxp[m >> 9][m & 511];
            float g0 = xm.x - nx, g1 = xm.y - ny, g2 = xm.z - nz;
            float t0 = sbe[0] + sce[0]  * g0 + sce[1]  * g1 + sce[2]  * g2
                              + sce[3]  * nx + sce[4]  * ny + sce[5]  * nz;
            float t1 = sbe[1] + sce[6]  * g0 + sce[7]  * g1 + sce[8]  * g2
                              + sce[9]  * nx + sce[10] * ny + sce[11] * nz;
            float t2 = sbe[2] + sce[12] * g0 + sce[13] * g1 + sce[14] * g2
                              + sce[15] * nx + sce[16] * ny + sce[17] * nz;
            h0 = fmaxf(h0, t0); h1 = fmaxf(h1, t1); h2 = fmaxf(h2, t2);
        }
        const int bq = (n & 63) * 3;
        float o0 = h0 + bias[bq + 0];
        float o1 = h1 + bias[bq + 1];
        float o2 = h2 + bias[bq + 2];
        o0 = o0 >= 0.f ? o0 : 0.2f * o0;
        o1 = o1 >= 0.f ? o1 : 0.2f * o1;
        o2 = o2 >= 0.f ? o2 : 0.2f * o2;
        float* op = out + (size_t)(b * NPTS + n) * 3;
        op[0] = o0; op[1] = o1; op[2] = o2;
    }
}

// ============================================================
extern "C" void kernel_launch(void* const* d_in, const int* in_sizes, int n_in,
                              void* d_out, int out_size) {
    const float* t0  = (const float*)d_in[0];
    const float* t1  = (const float*)d_in[1];
    const float* t2  = (const float*)d_in[2];
    const float* t3  = (const float*)d_in[3];
    const float* t4  = (const float*)d_in[4];
    const float* t5  = (const float*)d_in[5];
    const float* Wr0 = (const float*)d_in[6];
    const float* Wr1 = (const float*)d_in[7];
    const float* Wr2 = (const float*)d_in[8];
    const float* Wr3 = (const float*)d_in[9];
    const float* Wr4 = (const float*)d_in[10];
    const float* Wr5 = (const float*)d_in[11];
    const float* Wb  = (const float*)d_in[12];
    const float* Wl1 = (const float*)d_in[13];
    const float* Wl2 = (const float*)d_in[14];
    const float* bia = (const float*)d_in[15];
    const float* c1w = (const float*)d_in[16];
    const float* c1b = (const float*)d_in[17];
    const float* c2w = (const float*)d_in[18];
    const float* c2b = (const float*)d_in[19];

    k0_prep<<<641, 128>>>(t0, t1, t2, t3, t4, t5,
                          Wr0, Wr1, Wr2, Wr3, Wr4, Wr5,
                          Wl1, Wl2, c1w, c1b, c2w, c2b);
    k1_branch<<<NNODE * 16, 128>>>(t5, Wb);
    k2_knn<<<BATCH * 32, 256>>>(bia, (float*)d_out);
}

// round 4
// speedup vs baseline: 1.6330x; 1.6330x over previous
#include <cuda_runtime.h>

#define BATCH 16
#define NNODE 32
#define DEG 64
#define KNN 8
#define IN_F 128
#define OUT_F 3
#define NPTS 2048   // NNODE*DEG
#define JCOLS 8192  // DEG*IN_F

// ---------- device scratch (no allocations allowed) ----------
__device__ float  g_root[BATCH * NNODE * OUT_F];
__device__ float  g_Wl[IN_F * OUT_F];     // collapsed Wl1@Wl2, layout [f*3+o]
__device__ float  g_ceff[OUT_F * 6];      // collapsed c2w@c1w, layout [p*6+c]
__device__ float  g_beff[OUT_F];          // c2w@c1b + c2b
__device__ float4 g_x[BATCH * NPTS];      // (x0,x1,x2, 0.5*||x||^2)

// ---------- packed f32x2 helpers ----------
__device__ __forceinline__ unsigned long long splat2(float w) {
    unsigned long long r;
    asm("mov.b64 %0, {%1, %1};" : "=l"(r) : "f"(w));
    return r;
}
__device__ __forceinline__ void ffma2(unsigned long long& d,
                                      unsigned long long a,
                                      unsigned long long b) {
    asm("fma.rn.f32x2 %0, %1, %2, %0;" : "+l"(d) : "l"(a), "l"(b));
}

__device__ __forceinline__ float wredsum(float v) {
    #pragma unroll
    for (int o = 16; o > 0; o >>= 1) v += __shfl_xor_sync(0xffffffffu, v, o);
    return v;
}

// ============================================================
// K0: parallel prep. 641 blocks x 128 threads (unchanged, 9.5us).
// ============================================================
__global__ __launch_bounds__(128) void k0_prep(
        const float* __restrict__ t0, const float* __restrict__ t1,
        const float* __restrict__ t2, const float* __restrict__ t3,
        const float* __restrict__ t4, const float* __restrict__ t5,
        const float* __restrict__ Wr0, const float* __restrict__ Wr1,
        const float* __restrict__ Wr2, const float* __restrict__ Wr3,
        const float* __restrict__ Wr4, const float* __restrict__ Wr5,
        const float* __restrict__ Wl1, const float* __restrict__ Wl2,
        const float* __restrict__ c1w, const float* __restrict__ c1b,
        const float* __restrict__ c2w, const float* __restrict__ c2b) {
    const int bid = blockIdx.x;
    const int tid = threadIdx.x;
    const int w   = tid >> 5, lane = tid & 31;
    __shared__ float red[4][3];

    if (bid < 512) {
        const int b = bid >> 5, n = bid & 31;
        float s0 = 0.f, s1 = 0.f, s2 = 0.f;
        for (int idx = tid; idx < 1120; idx += 128) {
            float v; const float* wp;
            if (idx < 96) {
                v = t0[b * 96 + idx];                           wp = Wr0 + idx * 3;
            } else if (idx < 352) {
                int i = idx - 96;
                v = t1[(b * 2  + (n >> 4)) * 256 + i];          wp = Wr1 + i * 3;
            } else if (idx < 608) {
                int i = idx - 352;
                v = t2[(b * 4  + (n >> 3)) * 256 + i];          wp = Wr2 + i * 3;
            } else if (idx < 864) {
                int i = idx - 608;
                v = t3[(b * 8  + (n >> 2)) * 256 + i];          wp = Wr3 + i * 3;
            } else if (idx < 992) {
                int i = idx - 864;
                v = t4[(b * 16 + (n >> 1)) * 128 + i];          wp = Wr4 + i * 3;
            } else {
                int i = idx - 992;
                v = t5[(b * 32 +  n      ) * 128 + i];          wp = Wr5 + i * 3;
            }
            s0 = fmaf(v, wp[0], s0); s1 = fmaf(v, wp[1], s1); s2 = fmaf(v, wp[2], s2);
        }
        s0 = wredsum(s0); s1 = wredsum(s1); s2 = wredsum(s2);
        if (lane == 0) { red[w][0] = s0; red[w][1] = s1; red[w][2] = s2; }
        __syncthreads();
        if (tid < 3)
            g_root[(b * NNODE + n) * 3 + tid] =
                red[0][tid] + red[1][tid] + red[2][tid] + red[3][tid];
    } else if (bid < 640) {
        const int f = bid - 512;
        float s0 = 0.f, s1 = 0.f, s2 = 0.f;
        for (int tt = tid; tt < 1280; tt += 128) {
            float v = Wl1[f * 1280 + tt];
            s0 = fmaf(v, Wl2[tt * 3 + 0], s0);
            s1 = fmaf(v, Wl2[tt * 3 + 1], s1);
            s2 = fmaf(v, Wl2[tt * 3 + 2], s2);
        }
        s0 = wredsum(s0); s1 = wredsum(s1); s2 = wredsum(s2);
        if (lane == 0) { red[w][0] = s0; red[w][1] = s1; red[w][2] = s2; }
        __syncthreads();
        if (tid < 3)
            g_Wl[f * 3 + tid] =
                red[0][tid] + red[1][tid] + red[2][tid] + red[3][tid];
    } else {
        if (tid < 18) {
            int p = tid / 6, c = tid % 6;
            float s = 0.f;
            for (int o = 0; o < 64; o++) s = fmaf(c2w[p * 64 + o], c1w[o * 6 + c], s);
            g_ceff[tid] = s;
        } else if (tid < 21) {
            int p = tid - 18;
            float s = c2b[p];
            for (int o = 0; o < 64; o++) s = fmaf(c2w[p * 64 + o], c1b[o], s);
            g_beff[p] = s;
        }
    }
}

// ============================================================
// K1: identical to the R2 (138.9us) version — control variable this round.
// ============================================================
__global__ __launch_bounds__(128) void k1_branch(const float* __restrict__ t5,
                                                 const float* __restrict__ Wb) {
    const int n   = blockIdx.x >> 4;
    const int jt  = blockIdx.x & 15;
    const int j0  = jt * 512;
    const int tid = threadIdx.x;

    __shared__ __align__(16) unsigned long long sa[IN_F * 8];
    __shared__ float sC[16][513];
    __shared__ float sWl[IN_F * OUT_F];

    {
        int i = tid;
        #pragma unroll
        for (int p = 0; p < 8; p++) {
            float a0 = t5[((2 * p)     * NNODE + n) * IN_F + i];
            float a1 = t5[((2 * p + 1) * NNODE + n) * IN_F + i];
            sa[i * 8 + p] = ((unsigned long long)__float_as_uint(a1) << 32)
                          | (unsigned long long)__float_as_uint(a0);
        }
        for (int q = tid; q < IN_F * OUT_F; q += 128) sWl[q] = g_Wl[q];
    }
    __syncthreads();

    unsigned long long acc[4][8];
    #pragma unroll
    for (int c = 0; c < 4; c++)
        #pragma unroll
        for (int p = 0; p < 8; p++) acc[c][p] = 0ull;

    const float4* wptr =
        (const float4*)(Wb + (size_t)n * IN_F * JCOLS + j0 + 4 * tid);

    #pragma unroll 4
    for (int i = 0; i < IN_F; i++) {
        float4 w = wptr[(size_t)i * (JCOLS / 4)];
        unsigned long long w0 = splat2(w.x), w1 = splat2(w.y),
                           w2 = splat2(w.z), w3 = splat2(w.w);
        const ulonglong2* sap = (const ulonglong2*)(sa + i * 8);
        #pragma unroll
        for (int q = 0; q < 4; q++) {
            ulonglong2 ap = sap[q];
            ffma2(acc[0][2 * q], ap.x, w0);
            ffma2(acc[1][2 * q], ap.x, w1);
            ffma2(acc[2][2 * q], ap.x, w2);
            ffma2(acc[3][2 * q], ap.x, w3);
            ffma2(acc[0][2 * q + 1], ap.y, w0);
            ffma2(acc[1][2 * q + 1], ap.y, w1);
            ffma2(acc[2][2 * q + 1], ap.y, w2);
            ffma2(acc[3][2 * q + 1], ap.y, w3);
        }
    }

    #pragma unroll
    for (int c = 0; c < 4; c++) {
        int j = 4 * tid + c;
        #pragma unroll
        for (int p = 0; p < 8; p++) {
            float lo = __uint_as_float((unsigned)(acc[c][p] & 0xffffffffu));
            float hi = __uint_as_float((unsigned)(acc[c][p] >> 32));
            lo = lo >= 0.f ? lo : 0.2f * lo;
            hi = hi >= 0.f ? hi : 0.2f * hi;
            sC[2 * p][j]     = lo;
            sC[2 * p + 1][j] = hi;
        }
    }
    __syncthreads();

    if (tid < 64) {
        int d = tid >> 4, b = tid & 15;
        float s0 = 0.f, s1 = 0.f, s2 = 0.f;
        const float* row = &sC[b][d * 128];
        #pragma unroll 4
        for (int f = 0; f < 128; f++) {
            float cv = row[f];
            s0 = fmaf(cv, sWl[f * 3 + 0], s0);
            s1 = fmaf(cv, sWl[f * 3 + 1], s1);
            s2 = fmaf(cv, sWl[f * 3 + 2], s2);
        }
        const float* rp = &g_root[(b * NNODE + n) * 3];
        float x0 = s0 + rp[0], x1 = s1 + rp[1], x2 = s2 + rp[2];
        float hxx = 0.5f * (x0 * x0 + x1 * x1 + x2 * x2);
        int dglob = jt * 4 + d;
        g_x[b * NPTS + n * DEG + dglob] = make_float4(x0, x1, x2, hxx);
    }
}

// ============================================================
// K2: 2 lanes per point, 1024 candidates each; branchless uniform
// insert (fixed-cost carry chain, no divergent bubble); prefetched
// candidate groups; single shfl + bitonic-split set-merge.
// ============================================================
__device__ __forceinline__ void topk_ins(float v, int m, float* val, int* idx) {
    float cv = v; int ci = m;
    #pragma unroll
    for (int s = 0; s < KNN; s++) {
        bool gt = cv > val[s];          // strict: existing (earlier idx) wins ties
        float ov = val[s]; int oi = idx[s];
        val[s] = gt ? cv : ov;
        idx[s] = gt ? ci : oi;
        cv = gt ? ov : cv;
        ci = gt ? oi : ci;
    }
}

__global__ __launch_bounds__(128) void k2_knn(const float* __restrict__ bias,
                                              float* __restrict__ out) {
    const int b    = blockIdx.x >> 5;    // 16 batches x 32 tiles of 64 points
    const int tile = blockIdx.x & 31;
    const int tid  = threadIdx.x;

    __shared__ float4 sxp[2][1028];      // halves offset 1028*4=4112 words (=16 mod 32 banks)
    __shared__ float  sce[18], sbe[3];
    for (int q = tid; q < NPTS; q += 128)
        sxp[q >> 10][q & 1023] = g_x[b * NPTS + q];
    if (tid < 18) sce[tid] = g_ceff[tid];
    if (tid < 3)  sbe[tid] = g_beff[tid];
    __syncthreads();

    const int p = tid >> 1;              // point within tile (0..63)
    const int n = tile * 64 + p;         // point within batch
    const int c = tid & 1;               // half of the candidate set
    const float4 xn = sxp[n >> 10][n & 1023];
    const float nx = xn.x, ny = xn.y, nz = xn.z, negw = -xn.w;

    float val[KNN]; int idx[KNN];
    #pragma unroll
    for (int k = 0; k < KNN; k++) { val[k] = -3.4e38f; idx[k] = 0; }

    const float4* sec = sxp[c];
    const int mbase = c * 1024;

    float4 A = sec[0], Bv = sec[1], Cv = sec[2], Dv = sec[3];
    #pragma unroll 1
    for (int m0 = 0; m0 < 1024; m0 += 4) {
        float4 xa = A, xb = Bv, xc = Cv, xd = Dv;
        if (m0 + 4 < 1024) {             // prefetch next group before insert branch
            A  = sec[m0 + 4]; Bv = sec[m0 + 5];
            Cv = sec[m0 + 6]; Dv = sec[m0 + 7];
        }
        float p0 = fmaf(nx, xa.x, fmaf(ny, xa.y, fmaf(nz, xa.z, negw - xa.w)));
        float p1 = fmaf(nx, xb.x, fmaf(ny, xb.y, fmaf(nz, xb.z, negw - xb.w)));
        float p2 = fmaf(nx, xc.x, fmaf(ny, xc.y, fmaf(nz, xc.z, negw - xc.w)));
        float p3 = fmaf(nx, xd.x, fmaf(ny, xd.y, fmaf(nz, xd.z, negw - xd.w)));
        float gm = fmaxf(fmaxf(p0, p1), fmaxf(p2, p3));
        if (gm > val[KNN - 1]) {
            if (p0 > val[KNN - 1]) topk_ins(p0, mbase + m0,     val, idx);
            if (p1 > val[KNN - 1]) topk_ins(p1, mbase + m0 + 1, val, idx);
            if (p2 > val[KNN - 1]) topk_ins(p2, mbase + m0 + 2, val, idx);
            if (p3 > val[KNN - 1]) topk_ins(p3, mbase + m0 + 3, val, idx);
        }
    }

    // single merge: lane c==0 absorbs lane c==1 (bitonic split -> top-8 set)
    {
        float bv[KNN]; int bi[KNN];
        #pragma unroll
        for (int k = 0; k < KNN; k++) {
            bv[k] = __shfl_down_sync(0xffffffffu, val[k], 1);
            bi[k] = __shfl_down_sync(0xffffffffu, idx[k], 1);
        }
        if (c == 0) {
            #pragma unroll
            for (int i = 0; i < KNN; i++) {
                bool ga = (val[i] > bv[7 - i]) ||
                          (val[i] == bv[7 - i] && idx[i] < bi[7 - i]);
                val[i] = ga ? val[i] : bv[7 - i];
                idx[i] = ga ? idx[i] : bi[7 - i];
            }
        }
    }

    if (c == 0) {
        float h0 = -3.4e38f, h1 = -3.4e38f, h2 = -3.4e38f;
        #pragma unroll
        for (int k = 0; k < KNN; k++) {
            int m = idx[k];
            float4 xm = sxp[m >> 10][m & 1023];
            float g0 = xm.x - nx, g1 = xm.y - ny, g2 = xm.z - nz;
            float t0 = sbe[0] + sce[0]  * g0 + sce[1]  * g1 + sce[2]  * g2
                              + sce[3]  * nx + sce[4]  * ny + sce[5]  * nz;
            float t1 = sbe[1] + sce[6]  * g0 + sce[7]  * g1 + sce[8]  * g2
                              + sce[9]  * nx + sce[10] * ny + sce[11] * nz;
            float t2 = sbe[2] + sce[12] * g0 + sce[13] * g1 + sce[14] * g2
                              + sce[15] * nx + sce[16] * ny + sce[17] * nz;
            h0 = fmaxf(h0, t0); h1 = fmaxf(h1, t1); h2 = fmaxf(h2, t2);
        }
        const int bq = (n & 63) * 3;
        float o0 = h0 + bias[bq + 0];
        float o1 = h1 + bias[bq + 1];
        float o2 = h2 + bias[bq + 2];
        o0 = o0 >= 0.f ? o0 : 0.2f * o0;
        o1 = o1 >= 0.f ? o1 : 0.2f * o1;
        o2 = o2 >= 0.f ? o2 : 0.2f * o2;
        float* op = out + (size_t)(b * NPTS + n) * 3;
        op[0] = o0; op[1] = o1; op[2] = o2;
    }
}

// ============================================================
extern "C" void kernel_launch(void* const* d_in, const int* in_sizes, int n_in,
                              void* d_out, int out_size) {
    const float* t0  = (const float*)d_in[0];
    const float* t1  = (const float*)d_in[1];
    const float* t2  = (const float*)d_in[2];
    const float* t3  = (const float*)d_in[3];
    const float* t4  = (const float*)d_in[4];
    const float* t5  = (const float*)d_in[5];
    const float* Wr0 = (const float*)d_in[6];
    const float* Wr1 = (const float*)d_in[7];
    const float* Wr2 = (const float*)d_in[8];
    const float* Wr3 = (const float*)d_in[9];
    const float* Wr4 = (const float*)d_in[10];
    const float* Wr5 = (const float*)d_in[11];
    const float* Wb  = (const float*)d_in[12];
    const float* Wl1 = (const float*)d_in[13];
    const float* Wl2 = (const float*)d_in[14];
    const float* bia = (const float*)d_in[15];
    const float* c1w = (const float*)d_in[16];
    const float* c1b = (const float*)d_in[17];
    const float* c2w = (const float*)d_in[18];
    const float* c2b = (const float*)d_in[19];

    k0_prep<<<641, 128>>>(t0, t1, t2, t3, t4, t5,
                          Wr0, Wr1, Wr2, Wr3, Wr4, Wr5,
                          Wl1, Wl2, c1w, c1b, c2w, c2b);
    k1_branch<<<NNODE * 16, 128>>>(t5, Wb);
    k2_knn<<<BATCH * 32, 128>>>(bia, (float*)d_out);
}

// round 6
// speedup vs baseline: 1.6590x; 1.0159x over previous
#include <cuda_runtime.h>

#define BATCH 16
#define NNODE 32
#define DEG 64
#define KNN 8
#define IN_F 128
#define OUT_F 3
#define NPTS 2048   // NNODE*DEG
#define JCOLS 8192  // DEG*IN_F

// ---------- device scratch (no allocations allowed) ----------
__device__ float  g_root[BATCH * NNODE * OUT_F];
__device__ float  g_Wl[IN_F * OUT_F];     // collapsed Wl1@Wl2, layout [f*3+o]
__device__ float  g_ceff[OUT_F * 6];      // collapsed c2w@c1w, layout [p*6+c]
__device__ float  g_beff[OUT_F];          // c2w@c1b + c2b
__device__ float4 g_x[BATCH * NPTS];      // (x0,x1,x2, 0.5*||x||^2)

// ---------- packed f32x2 helpers ----------
__device__ __forceinline__ unsigned long long splat2(float w) {
    unsigned long long r;
    asm("mov.b64 %0, {%1, %1};" : "=l"(r) : "f"(w));
    return r;
}
__device__ __forceinline__ void ffma2(unsigned long long& d,
                                      unsigned long long a,
                                      unsigned long long b) {
    asm("fma.rn.f32x2 %0, %1, %2, %0;" : "+l"(d) : "l"(a), "l"(b));
}

__device__ __forceinline__ float wredsum(float v) {
    #pragma unroll
    for (int o = 16; o > 0; o >>= 1) v += __shfl_xor_sync(0xffffffffu, v, o);
    return v;
}

// ============================================================
// K0: parallel prep (unchanged — measured 9.5us).
// ============================================================
__global__ __launch_bounds__(128) void k0_prep(
        const float* __restrict__ t0, const float* __restrict__ t1,
        const float* __restrict__ t2, const float* __restrict__ t3,
        const float* __restrict__ t4, const float* __restrict__ t5,
        const float* __restrict__ Wr0, const float* __restrict__ Wr1,
        const float* __restrict__ Wr2, const float* __restrict__ Wr3,
        const float* __restrict__ Wr4, const float* __restrict__ Wr5,
        const float* __restrict__ Wl1, const float* __restrict__ Wl2,
        const float* __restrict__ c1w, const float* __restrict__ c1b,
        const float* __restrict__ c2w, const float* __restrict__ c2b) {
    const int bid = blockIdx.x;
    const int tid = threadIdx.x;
    const int w   = tid >> 5, lane = tid & 31;
    __shared__ float red[4][3];

    if (bid < 512) {
        const int b = bid >> 5, n = bid & 31;
        float s0 = 0.f, s1 = 0.f, s2 = 0.f;
        for (int idx = tid; idx < 1120; idx += 128) {
            float v; const float* wp;
            if (idx < 96) {
                v = t0[b * 96 + idx];                           wp = Wr0 + idx * 3;
            } else if (idx < 352) {
                int i = idx - 96;
                v = t1[(b * 2  + (n >> 4)) * 256 + i];          wp = Wr1 + i * 3;
            } else if (idx < 608) {
                int i = idx - 352;
                v = t2[(b * 4  + (n >> 3)) * 256 + i];          wp = Wr2 + i * 3;
            } else if (idx < 864) {
                int i = idx - 608;
                v = t3[(b * 8  + (n >> 2)) * 256 + i];          wp = Wr3 + i * 3;
            } else if (idx < 992) {
                int i = idx - 864;
                v = t4[(b * 16 + (n >> 1)) * 128 + i];          wp = Wr4 + i * 3;
            } else {
                int i = idx - 992;
                v = t5[(b * 32 +  n      ) * 128 + i];          wp = Wr5 + i * 3;
            }
            s0 = fmaf(v, wp[0], s0); s1 = fmaf(v, wp[1], s1); s2 = fmaf(v, wp[2], s2);
        }
        s0 = wredsum(s0); s1 = wredsum(s1); s2 = wredsum(s2);
        if (lane == 0) { red[w][0] = s0; red[w][1] = s1; red[w][2] = s2; }
        __syncthreads();
        if (tid < 3)
            g_root[(b * NNODE + n) * 3 + tid] =
                red[0][tid] + red[1][tid] + red[2][tid] + red[3][tid];
    } else if (bid < 640) {
        const int f = bid - 512;
        float s0 = 0.f, s1 = 0.f, s2 = 0.f;
        for (int tt = tid; tt < 1280; tt += 128) {
            float v = Wl1[f * 1280 + tt];
            s0 = fmaf(v, Wl2[tt * 3 + 0], s0);
            s1 = fmaf(v, Wl2[tt * 3 + 1], s1);
            s2 = fmaf(v, Wl2[tt * 3 + 2], s2);
        }
        s0 = wredsum(s0); s1 = wredsum(s1); s2 = wredsum(s2);
        if (lane == 0) { red[w][0] = s0; red[w][1] = s1; red[w][2] = s2; }
        __syncthreads();
        if (tid < 3)
            g_Wl[f * 3 + tid] =
                red[0][tid] + red[1][tid] + red[2][tid] + red[3][tid];
    } else {
        if (tid < 18) {
            int p = tid / 6, c = tid % 6;
            float s = 0.f;
            for (int o = 0; o < 64; o++) s = fmaf(c2w[p * 64 + o], c1w[o * 6 + c], s);
            g_ceff[tid] = s;
        } else if (tid < 21) {
            int p = tid - 18;
            float s = c2b[p];
            for (int o = 0; o < 64; o++) s = fmaf(c2w[p * 64 + o], c1b[o], s);
            g_beff[p] = s;
        }
    }
}

// ============================================================
// K1: 256 threads/block, 2 cols/thread -> 8 ULL accumulators.
// FIX vs R5: sWl staging now strided over all 384 entries (was only 256
// -> garbage weights for features 85..127, rel_err 3e-2).
// ============================================================
__global__ __launch_bounds__(256) void k1_branch(const float* __restrict__ t5,
                                                 const float* __restrict__ Wb) {
    const int n   = blockIdx.x >> 4;
    const int jt  = blockIdx.x & 15;
    const int j0  = jt * 512;
    const int tid = threadIdx.x;

    __shared__ __align__(16) unsigned long long sa[IN_F * 8];  // [i][bpair]
    __shared__ __align__(8) float sC[16][516];
    __shared__ float sWl[IN_F * OUT_F];

    {
        // 256 threads fill sa: thread handles (i = tid&127, phalf = tid>>7)
        int i = tid & 127, ph = (tid >> 7) * 4;
        #pragma unroll
        for (int pp = 0; pp < 4; pp++) {
            int p = ph + pp;
            float a0 = t5[((2 * p)     * NNODE + n) * IN_F + i];
            float a1 = t5[((2 * p + 1) * NNODE + n) * IN_F + i];
            sa[i * 8 + p] = ((unsigned long long)__float_as_uint(a1) << 32)
                          | (unsigned long long)__float_as_uint(a0);
        }
        for (int q = tid; q < IN_F * OUT_F; q += 256) sWl[q] = g_Wl[q];
    }
    __syncthreads();

    unsigned long long acc[2][8];
    #pragma unroll
    for (int c = 0; c < 2; c++)
        #pragma unroll
        for (int p = 0; p < 8; p++) acc[c][p] = 0ull;

    const float2* wptr =
        (const float2*)(Wb + (size_t)n * IN_F * JCOLS + j0 + 2 * tid);

    #pragma unroll 8
    for (int i = 0; i < IN_F; i++) {
        float2 w = wptr[(size_t)i * (JCOLS / 2)];
        unsigned long long w0 = splat2(w.x), w1 = splat2(w.y);
        const ulonglong2* sap = (const ulonglong2*)(sa + i * 8);
        #pragma unroll
        for (int q = 0; q < 4; q++) {
            ulonglong2 ap = sap[q];
            ffma2(acc[0][2 * q],     ap.x, w0);
            ffma2(acc[1][2 * q],     ap.x, w1);
            ffma2(acc[0][2 * q + 1], ap.y, w0);
            ffma2(acc[1][2 * q + 1], ap.y, w1);
        }
    }

    // leaky -> sC (float2 stores: row 2p gets (col0,col1) lows, row 2p+1 highs)
    #pragma unroll
    for (int p = 0; p < 8; p++) {
        float l0 = __uint_as_float((unsigned)(acc[0][p] & 0xffffffffu));
        float h0 = __uint_as_float((unsigned)(acc[0][p] >> 32));
        float l1 = __uint_as_float((unsigned)(acc[1][p] & 0xffffffffu));
        float h1 = __uint_as_float((unsigned)(acc[1][p] >> 32));
        l0 = l0 >= 0.f ? l0 : 0.2f * l0;
        h0 = h0 >= 0.f ? h0 : 0.2f * h0;
        l1 = l1 >= 0.f ? l1 : 0.2f * l1;
        h1 = h1 >= 0.f ? h1 : 0.2f * h1;
        *(float2*)&sC[2 * p][2 * tid]     = make_float2(l0, l1);
        *(float2*)&sC[2 * p + 1][2 * tid] = make_float2(h0, h1);
    }
    __syncthreads();

    // projection: thread t<64 handles one (d,b)
    if (tid < 64) {
        int d = tid >> 4, b = tid & 15;
        float s0 = 0.f, s1 = 0.f, s2 = 0.f;
        const float* row = &sC[b][d * 128];
        #pragma unroll 4
        for (int f = 0; f < 128; f++) {
            float cv = row[f];
            s0 = fmaf(cv, sWl[f * 3 + 0], s0);
            s1 = fmaf(cv, sWl[f * 3 + 1], s1);
            s2 = fmaf(cv, sWl[f * 3 + 2], s2);
        }
        const float* rp = &g_root[(b * NNODE + n) * 3];
        float x0 = s0 + rp[0], x1 = s1 + rp[1], x2 = s2 + rp[2];
        float hxx = 0.5f * (x0 * x0 + x1 * x1 + x2 * x2);
        int dglob = jt * 4 + d;
        g_x[b * NPTS + n * DEG + dglob] = make_float4(x0, x1, x2, hxx);
    }
}

// ============================================================
// K2: ONE lane per point (strongest threshold -> fewest true inserts),
// 64-thr blocks (grid 512). Branchless carry-chain insert; group-of-4
// prefilter; prefetch. Then collapsed edge-MLP + max + bias + leaky.
// ============================================================
__device__ __forceinline__ void topk_ins(float v, int m, float* val, int* idx) {
    float cv = v; int ci = m;
    #pragma unroll
    for (int s = 0; s < KNN; s++) {
        bool gt = cv > val[s];          // strict: existing (earlier idx) wins ties
        float ov = val[s]; int oi = idx[s];
        val[s] = gt ? cv : ov;
        idx[s] = gt ? ci : oi;
        cv = gt ? ov : cv;
        ci = gt ? oi : ci;
    }
}

__global__ __launch_bounds__(64) void k2_knn(const float* __restrict__ bias,
                                             float* __restrict__ out) {
    const int b    = blockIdx.x >> 5;    // 16 batches x 32 chunks of 64 points
    const int chnk = blockIdx.x & 31;
    const int tid  = threadIdx.x;

    __shared__ float4 sx[NPTS];          // 32KB, broadcast reads in scan
    __shared__ float  sce[18], sbe[3];
    #pragma unroll
    for (int q = 0; q < NPTS / 64; q++)
        sx[q * 64 + tid] = g_x[b * NPTS + q * 64 + tid];
    if (tid < 18) sce[tid] = g_ceff[tid];
    if (tid < 3)  sbe[tid] = g_beff[tid];
    __syncthreads();

    const int n = chnk * 64 + tid;       // this thread's point
    const float4 xn = sx[n];
    const float nx = xn.x, ny = xn.y, nz = xn.z, negw = -xn.w;

    float val[KNN]; int idx[KNN];
    #pragma unroll
    for (int k = 0; k < KNN; k++) { val[k] = -3.4e38f; idx[k] = 0; }

    float4 A = sx[0], Bv = sx[1], Cv = sx[2], Dv = sx[3];
    #pragma unroll 1
    for (int m0 = 0; m0 < NPTS; m0 += 4) {
        float4 xa = A, xb = Bv, xc = Cv, xd = Dv;
        if (m0 + 4 < NPTS) {             // prefetch next group before branches
            A  = sx[m0 + 4]; Bv = sx[m0 + 5];
            Cv = sx[m0 + 6]; Dv = sx[m0 + 7];
        }
        float p0 = fmaf(nx, xa.x, fmaf(ny, xa.y, fmaf(nz, xa.z, negw - xa.w)));
        float p1 = fmaf(nx, xb.x, fmaf(ny, xb.y, fmaf(nz, xb.z, negw - xb.w)));
        float p2 = fmaf(nx, xc.x, fmaf(ny, xc.y, fmaf(nz, xc.z, negw - xc.w)));
        float p3 = fmaf(nx, xd.x, fmaf(ny, xd.y, fmaf(nz, xd.z, negw - xd.w)));
        float gm = fmaxf(fmaxf(p0, p1), fmaxf(p2, p3));
        if (gm > val[KNN - 1]) {
            if (p0 > val[KNN - 1]) topk_ins(p0, m0,     val, idx);
            if (p1 > val[KNN - 1]) topk_ins(p1, m0 + 1, val, idx);
            if (p2 > val[KNN - 1]) topk_ins(p2, m0 + 2, val, idx);
            if (p3 > val[KNN - 1]) topk_ins(p3, m0 + 3, val, idx);
        }
    }

    float h0 = -3.4e38f, h1 = -3.4e38f, h2 = -3.4e38f;
    #pragma unroll
    for (int k = 0; k < KNN; k++) {
        float4 xm = sx[idx[k]];
        float g0 = xm.x - nx, g1 = xm.y - ny, g2 = xm.z - nz;
        float t0 = sbe[0] + sce[0]  * g0 + sce[1]  * g1 + sce[2]  * g2
                          + sce[3]  * nx + sce[4]  * ny + sce[5]  * nz;
        float t1 = sbe[1] + sce[6]  * g0 + sce[7]  * g1 + sce[8]  * g2
                          + sce[9]  * nx + sce[10] * ny + sce[11] * nz;
        float t2 = sbe[2] + sce[12] * g0 + sce[13] * g1 + sce[14] * g2
                          + sce[15] * nx + sce[16] * ny + sce[17] * nz;
        h0 = fmaxf(h0, t0); h1 = fmaxf(h1, t1); h2 = fmaxf(h2, t2);
    }

    const int bq = tid * 3;              // bias tiled with period DEG=64; n&63==tid
    float o0 = h0 + bias[bq + 0];
    float o1 = h1 + bias[bq + 1];
    float o2 = h2 + bias[bq + 2];
    o0 = o0 >= 0.f ? o0 : 0.2f * o0;
    o1 = o1 >= 0.f ? o1 : 0.2f * o1;
    o2 = o2 >= 0.f ? o2 : 0.2f * o2;

    float* op = out + (size_t)(b * NPTS + n) * 3;
    op[0] = o0; op[1] = o1; op[2] = o2;
}

// ============================================================
extern "C" void kernel_launch(void* const* d_in, const int* in_sizes, int n_in,
                              void* d_out, int out_size) {
    const float* t0  = (const float*)d_in[0];
    const float* t1  = (const float*)d_in[1];
    const float* t2  = (const float*)d_in[2];
    const float* t3  = (const float*)d_in[3];
    const float* t4  = (const float*)d_in[4];
    const float* t5  = (const float*)d_in[5];
    const float* Wr0 = (const float*)d_in[6];
    const float* Wr1 = (const float*)d_in[7];
    const float* Wr2 = (const float*)d_in[8];
    const float* Wr3 = (const float*)d_in[9];
    const float* Wr4 = (const float*)d_in[10];
    const float* Wr5 = (const float*)d_in[11];
    const float* Wb  = (const float*)d_in[12];
    const float* Wl1 = (const float*)d_in[13];
    const float* Wl2 = (const float*)d_in[14];
    const float* bia = (const float*)d_in[15];
    const float* c1w = (const float*)d_in[16];
    const float* c1b = (const float*)d_in[17];
    const float* c2w = (const float*)d_in[18];
    const float* c2b = (const float*)d_in[19];

    k0_prep<<<641, 128>>>(t0, t1, t2, t3, t4, t5,
                          Wr0, Wr1, Wr2, Wr3, Wr4, Wr5,
                          Wl1, Wl2, c1w, c1b, c2w, c2b);
    k1_branch<<<NNODE * 16, 256>>>(t5, Wb);
    k2_knn<<<BATCH * 32, 64>>>(bia, (float*)d_out);
}

// round 7
// speedup vs baseline: 1.7300x; 1.0428x over previous
#include <cuda_runtime.h>

#define BATCH 16
#define NNODE 32
#define DEG 64
#define KNN 8
#define IN_F 128
#define OUT_F 3
#define NPTS 2048   // NNODE*DEG
#define JCOLS 8192  // DEG*IN_F

typedef unsigned long long ull;

// ---------- device scratch (no allocations allowed) ----------
__device__ float  g_root[BATCH * NNODE * OUT_F];
__device__ float  g_Wl[IN_F * OUT_F];     // collapsed Wl1@Wl2, layout [f*3+o]
__device__ float  g_ceff[OUT_F * 6];      // collapsed c2w@c1w, layout [p*6+c]
__device__ float  g_beff[OUT_F];          // c2w@c1b + c2b
__device__ float4 g_x[BATCH * NPTS];      // (x0,x1,x2, 0.5*||x||^2)

// ---------- packed f32x2 helpers ----------
__device__ __forceinline__ ull splat2(float w) {
    ull r;
    asm("mov.b64 %0, {%1, %1};" : "=l"(r) : "f"(w));
    return r;
}
__device__ __forceinline__ void ffma2(ull& d, ull a, ull b) {
    asm("fma.rn.f32x2 %0, %1, %2, %0;" : "+l"(d) : "l"(a), "l"(b));
}
__device__ __forceinline__ ull ffma2r(ull a, ull b, ull c) {
    ull d;
    asm("fma.rn.f32x2 %0, %1, %2, %3;" : "=l"(d) : "l"(a), "l"(b), "l"(c));
    return d;
}
__device__ __forceinline__ ull add2r(ull a, ull b) {
    ull d;
    asm("add.rn.f32x2 %0, %1, %2;" : "=l"(d) : "l"(a), "l"(b));
    return d;
}
__device__ __forceinline__ float lo2(ull v) {
    return __uint_as_float((unsigned)(v & 0xffffffffu));
}
__device__ __forceinline__ float hi2(ull v) {
    return __uint_as_float((unsigned)(v >> 32));
}

__device__ __forceinline__ float wredsum(float v) {
    #pragma unroll
    for (int o = 16; o > 0; o >>= 1) v += __shfl_xor_sync(0xffffffffu, v, o);
    return v;
}

// ============================================================
// K0: parallel prep (unchanged — measured ~9.7us).
// ============================================================
__global__ __launch_bounds__(128) void k0_prep(
        const float* __restrict__ t0, const float* __restrict__ t1,
        const float* __restrict__ t2, const float* __restrict__ t3,
        const float* __restrict__ t4, const float* __restrict__ t5,
        const float* __restrict__ Wr0, const float* __restrict__ Wr1,
        const float* __restrict__ Wr2, const float* __restrict__ Wr3,
        const float* __restrict__ Wr4, const float* __restrict__ Wr5,
        const float* __restrict__ Wl1, const float* __restrict__ Wl2,
        const float* __restrict__ c1w, const float* __restrict__ c1b,
        const float* __restrict__ c2w, const float* __restrict__ c2b) {
    const int bid = blockIdx.x;
    const int tid = threadIdx.x;
    const int w   = tid >> 5, lane = tid & 31;
    __shared__ float red[4][3];

    if (bid < 512) {
        const int b = bid >> 5, n = bid & 31;
        float s0 = 0.f, s1 = 0.f, s2 = 0.f;
        for (int idx = tid; idx < 1120; idx += 128) {
            float v; const float* wp;
            if (idx < 96) {
                v = t0[b * 96 + idx];                           wp = Wr0 + idx * 3;
            } else if (idx < 352) {
                int i = idx - 96;
                v = t1[(b * 2  + (n >> 4)) * 256 + i];          wp = Wr1 + i * 3;
            } else if (idx < 608) {
                int i = idx - 352;
                v = t2[(b * 4  + (n >> 3)) * 256 + i];          wp = Wr2 + i * 3;
            } else if (idx < 864) {
                int i = idx - 608;
                v = t3[(b * 8  + (n >> 2)) * 256 + i];          wp = Wr3 + i * 3;
            } else if (idx < 992) {
                int i = idx - 864;
                v = t4[(b * 16 + (n >> 1)) * 128 + i];          wp = Wr4 + i * 3;
            } else {
                int i = idx - 992;
                v = t5[(b * 32 +  n      ) * 128 + i];          wp = Wr5 + i * 3;
            }
            s0 = fmaf(v, wp[0], s0); s1 = fmaf(v, wp[1], s1); s2 = fmaf(v, wp[2], s2);
        }
        s0 = wredsum(s0); s1 = wredsum(s1); s2 = wredsum(s2);
        if (lane == 0) { red[w][0] = s0; red[w][1] = s1; red[w][2] = s2; }
        __syncthreads();
        if (tid < 3)
            g_root[(b * NNODE + n) * 3 + tid] =
                red[0][tid] + red[1][tid] + red[2][tid] + red[3][tid];
    } else if (bid < 640) {
        const int f = bid - 512;
        float s0 = 0.f, s1 = 0.f, s2 = 0.f;
        for (int tt = tid; tt < 1280; tt += 128) {
            float v = Wl1[f * 1280 + tt];
            s0 = fmaf(v, Wl2[tt * 3 + 0], s0);
            s1 = fmaf(v, Wl2[tt * 3 + 1], s1);
            s2 = fmaf(v, Wl2[tt * 3 + 2], s2);
        }
        s0 = wredsum(s0); s1 = wredsum(s1); s2 = wredsum(s2);
        if (lane == 0) { red[w][0] = s0; red[w][1] = s1; red[w][2] = s2; }
        __syncthreads();
        if (tid < 3)
            g_Wl[f * 3 + tid] =
                red[0][tid] + red[1][tid] + red[2][tid] + red[3][tid];
    } else {
        if (tid < 18) {
            int p = tid / 6, c = tid % 6;
            float s = 0.f;
            for (int o = 0; o < 64; o++) s = fmaf(c2w[p * 64 + o], c1w[o * 6 + c], s);
            g_ceff[tid] = s;
        } else if (tid < 21) {
            int p = tid - 18;
            float s = c2b[p];
            for (int o = 0; o < 64; o++) s = fmaf(c2w[p * 64 + o], c1b[o], s);
            g_beff[p] = s;
        }
    }
}

// ============================================================
// K1: unchanged from R6 (passed, ~15-20us modeled).
// ============================================================
__global__ __launch_bounds__(256) void k1_branch(const float* __restrict__ t5,
                                                 const float* __restrict__ Wb) {
    const int n   = blockIdx.x >> 4;
    const int jt  = blockIdx.x & 15;
    const int j0  = jt * 512;
    const int tid = threadIdx.x;

    __shared__ __align__(16) ull sa[IN_F * 8];  // [i][bpair]
    __shared__ __align__(8) float sC[16][516];
    __shared__ float sWl[IN_F * OUT_F];

    {
        int i = tid & 127, ph = (tid >> 7) * 4;
        #pragma unroll
        for (int pp = 0; pp < 4; pp++) {
            int p = ph + pp;
            float a0 = t5[((2 * p)     * NNODE + n) * IN_F + i];
            float a1 = t5[((2 * p + 1) * NNODE + n) * IN_F + i];
            sa[i * 8 + p] = ((ull)__float_as_uint(a1) << 32)
                          | (ull)__float_as_uint(a0);
        }
        for (int q = tid; q < IN_F * OUT_F; q += 256) sWl[q] = g_Wl[q];
    }
    __syncthreads();

    ull acc[2][8];
    #pragma unroll
    for (int c = 0; c < 2; c++)
        #pragma unroll
        for (int p = 0; p < 8; p++) acc[c][p] = 0ull;

    const float2* wptr =
        (const float2*)(Wb + (size_t)n * IN_F * JCOLS + j0 + 2 * tid);

    #pragma unroll 8
    for (int i = 0; i < IN_F; i++) {
        float2 w = wptr[(size_t)i * (JCOLS / 2)];
        ull w0 = splat2(w.x), w1 = splat2(w.y);
        const ulonglong2* sap = (const ulonglong2*)(sa + i * 8);
        #pragma unroll
        for (int q = 0; q < 4; q++) {
            ulonglong2 ap = sap[q];
            ffma2(acc[0][2 * q],     ap.x, w0);
            ffma2(acc[1][2 * q],     ap.x, w1);
            ffma2(acc[0][2 * q + 1], ap.y, w0);
            ffma2(acc[1][2 * q + 1], ap.y, w1);
        }
    }

    #pragma unroll
    for (int p = 0; p < 8; p++) {
        float l0 = lo2(acc[0][p]), h0 = hi2(acc[0][p]);
        float l1 = lo2(acc[1][p]), h1 = hi2(acc[1][p]);
        l0 = l0 >= 0.f ? l0 : 0.2f * l0;
        h0 = h0 >= 0.f ? h0 : 0.2f * h0;
        l1 = l1 >= 0.f ? l1 : 0.2f * l1;
        h1 = h1 >= 0.f ? h1 : 0.2f * h1;
        *(float2*)&sC[2 * p][2 * tid]     = make_float2(l0, l1);
        *(float2*)&sC[2 * p + 1][2 * tid] = make_float2(h0, h1);
    }
    __syncthreads();

    if (tid < 64) {
        int d = tid >> 4, b = tid & 15;
        float s0 = 0.f, s1 = 0.f, s2 = 0.f;
        const float* row = &sC[b][d * 128];
        #pragma unroll 4
        for (int f = 0; f < 128; f++) {
            float cv = row[f];
            s0 = fmaf(cv, sWl[f * 3 + 0], s0);
            s1 = fmaf(cv, sWl[f * 3 + 1], s1);
            s2 = fmaf(cv, sWl[f * 3 + 2], s2);
        }
        const float* rp = &g_root[(b * NNODE + n) * 3];
        float x0 = s0 + rp[0], x1 = s1 + rp[1], x2 = s2 + rp[2];
        float hxx = 0.5f * (x0 * x0 + x1 * x1 + x2 * x2);
        int dglob = jt * 4 + d;
        g_x[b * NPTS + n * DEG + dglob] = make_float4(x0, x1, x2, hxx);
    }
}

// ============================================================
// K2: SoA candidates (X/Y/Z/ W'=-0.5||x||^2), packed f32x2 scoring
// (2 cands/op, register-alias halves), groups of 8 with one fmax-tree
// prefilter branch. Insert chain + tie semantics identical to R6.
// ============================================================
__device__ __forceinline__ void topk_ins(float v, int m, float* val, int* idx) {
    float cv = v; int ci = m;
    #pragma unroll
    for (int s = 0; s < KNN; s++) {
        bool gt = cv > val[s];          // strict: existing (earlier idx) wins ties
        float ov = val[s]; int oi = idx[s];
        val[s] = gt ? cv : ov;
        idx[s] = gt ? ci : oi;
        cv = gt ? ov : cv;
        ci = gt ? oi : ci;
    }
}

__global__ __launch_bounds__(64) void k2_knn(const float* __restrict__ bias,
                                             float* __restrict__ out) {
    const int b    = blockIdx.x >> 5;    // 16 batches x 32 chunks of 64 points
    const int chnk = blockIdx.x & 31;
    const int tid  = threadIdx.x;

    __shared__ __align__(16) float sX[NPTS], sY[NPTS], sZ[NPTS], sW[NPTS];
    __shared__ float sce[18], sbe[3];
    #pragma unroll
    for (int q = 0; q < NPTS / 64; q++) {
        int i = q * 64 + tid;
        float4 v = g_x[b * NPTS + i];
        sX[i] = v.x; sY[i] = v.y; sZ[i] = v.z; sW[i] = -v.w;
    }
    if (tid < 18) sce[tid] = g_ceff[tid];
    if (tid < 3)  sbe[tid] = g_beff[tid];
    __syncthreads();

    const int n = chnk * 64 + tid;       // this thread's point
    const float nx = sX[n], ny = sY[n], nz = sZ[n];
    const ull nx2 = splat2(nx), ny2 = splat2(ny), nz2 = splat2(nz);
    const ull c0  = splat2(sW[n]);       // = -0.5*||xn||^2

    float val[KNN]; int idx[KNN];
    #pragma unroll
    for (int k = 0; k < KNN; k++) { val[k] = -3.4e38f; idx[k] = 0; }

    const ulonglong2* pX = (const ulonglong2*)sX;   // 512 entries (4 cands each)
    const ulonglong2* pY = (const ulonglong2*)sY;
    const ulonglong2* pZ = (const ulonglong2*)sZ;
    const ulonglong2* pW = (const ulonglong2*)sW;

    ulonglong2 AX = pX[0], AY = pY[0], AZ = pZ[0], AW = pW[0];
    ulonglong2 BX = pX[1], BY = pY[1], BZ = pZ[1], BW = pW[1];

    #pragma unroll 1
    for (int g = 0; g < NPTS / 8; g++) {
        ulonglong2 cX = AX, cY = AY, cZ = AZ, cW = AW;
        ulonglong2 dX = BX, dY = BY, dZ = BZ, dW = BW;
        if (g < NPTS / 8 - 1) {          // prefetch next 8 candidates
            AX = pX[2 * g + 2]; AY = pY[2 * g + 2];
            AZ = pZ[2 * g + 2]; AW = pW[2 * g + 2];
            BX = pX[2 * g + 3]; BY = pY[2 * g + 3];
            BZ = pZ[2 * g + 3]; BW = pW[2 * g + 3];
        }
        // score = nx*x + ny*y + nz*z + (-hxx_n + w'), same op order as R6
        ull t0 = ffma2r(nx2, cX.x, ffma2r(ny2, cY.x, ffma2r(nz2, cZ.x, add2r(c0, cW.x))));
        ull t1 = ffma2r(nx2, cX.y, ffma2r(ny2, cY.y, ffma2r(nz2, cZ.y, add2r(c0, cW.y))));
        ull t2 = ffma2r(nx2, dX.x, ffma2r(ny2, dY.x, ffma2r(nz2, dZ.x, add2r(c0, dW.x))));
        ull t3 = ffma2r(nx2, dX.y, ffma2r(ny2, dY.y, ffma2r(nz2, dZ.y, add2r(c0, dW.y))));
        float s0 = lo2(t0), s1 = hi2(t0), s2 = lo2(t1), s3 = hi2(t1);
        float s4 = lo2(t2), s5 = hi2(t2), s6 = lo2(t3), s7 = hi2(t3);
        float gm = fmaxf(fmaxf(fmaxf(s0, s1), fmaxf(s2, s3)),
                         fmaxf(fmaxf(s4, s5), fmaxf(s6, s7)));
        if (gm > val[KNN - 1]) {
            const int m0 = g * 8;
            if (s0 > val[KNN - 1]) topk_ins(s0, m0 + 0, val, idx);
            if (s1 > val[KNN - 1]) topk_ins(s1, m0 + 1, val, idx);
            if (s2 > val[KNN - 1]) topk_ins(s2, m0 + 2, val, idx);
            if (s3 > val[KNN - 1]) topk_ins(s3, m0 + 3, val, idx);
            if (s4 > val[KNN - 1]) topk_ins(s4, m0 + 4, val, idx);
            if (s5 > val[KNN - 1]) topk_ins(s5, m0 + 5, val, idx);
            if (s6 > val[KNN - 1]) topk_ins(s6, m0 + 6, val, idx);
            if (s7 > val[KNN - 1]) topk_ins(s7, m0 + 7, val, idx);
        }
    }

    float h0 = -3.4e38f, h1 = -3.4e38f, h2 = -3.4e38f;
    #pragma unroll
    for (int k = 0; k < KNN; k++) {
        int m = idx[k];
        float mx = sX[m], my = sY[m], mz = sZ[m];
        float g0 = mx - nx, g1 = my - ny, g2 = mz - nz;
        float t0 = sbe[0] + sce[0]  * g0 + sce[1]  * g1 + sce[2]  * g2
                          + sce[3]  * nx + sce[4]  * ny + sce[5]  * nz;
        float t1 = sbe[1] + sce[6]  * g0 + sce[7]  * g1 + sce[8]  * g2
                          + sce[9]  * nx + sce[10] * ny + sce[11] * nz;
        float t2 = sbe[2] + sce[12] * g0 + sce[13] * g1 + sce[14] * g2
                          + sce[15] * nx + sce[16] * ny + sce[17] * nz;
        h0 = fmaxf(h0, t0); h1 = fmaxf(h1, t1); h2 = fmaxf(h2, t2);
    }

    const int bq = tid * 3;              // bias tiled with period DEG=64; n&63==tid
    float o0 = h0 + bias[bq + 0];
    float o1 = h1 + bias[bq + 1];
    float o2 = h2 + bias[bq + 2];
    o0 = o0 >= 0.f ? o0 : 0.2f * o0;
    o1 = o1 >= 0.f ? o1 : 0.2f * o1;
    o2 = o2 >= 0.f ? o2 : 0.2f * o2;

    float* op = out + (size_t)(b * NPTS + n) * 3;
    op[0] = o0; op[1] = o1; op[2] = o2;
}

// ============================================================
extern "C" void kernel_launch(void* const* d_in, const int* in_sizes, int n_in,
                              void* d_out, int out_size) {
    const float* t0  = (const float*)d_in[0];
    const float* t1  = (const float*)d_in[1];
    const float* t2  = (const float*)d_in[2];
    const float* t3  = (const float*)d_in[3];
    const float* t4  = (const float*)d_in[4];
    const float* t5  = (const float*)d_in[5];
    const float* Wr0 = (const float*)d_in[6];
    const float* Wr1 = (const float*)d_in[7];
    const float* Wr2 = (const float*)d_in[8];
    const float* Wr3 = (const float*)d_in[9];
    const float* Wr4 = (const float*)d_in[10];
    const float* Wr5 = (const float*)d_in[11];
    const float* Wb  = (const float*)d_in[12];
    const float* Wl1 = (const float*)d_in[13];
    const float* Wl2 = (const float*)d_in[14];
    const float* bia = (const float*)d_in[15];
    const float* c1w = (const float*)d_in[16];
    const float* c1b = (const float*)d_in[17];
    const float* c2w = (const float*)d_in[18];
    const float* c2b = (const float*)d_in[19];

    k0_prep<<<641, 128>>>(t0, t1, t2, t3, t4, t5,
                          Wr0, Wr1, Wr2, Wr3, Wr4, Wr5,
                          Wl1, Wl2, c1w, c1b, c2w, c2b);
    k1_branch<<<NNODE * 16, 256>>>(t5, Wb);
    k2_knn<<<BATCH * 32, 64>>>(bia, (float*)d_out);
}

// round 8
// speedup vs baseline: 2.0495x; 1.1846x over previous
#include <cuda_runtime.h>

#define BATCH 16
#define NNODE 32
#define DEG 64
#define KNN 8
#define IN_F 128
#define OUT_F 3
#define NPTS 2048   // NNODE*DEG
#define JCOLS 8192  // DEG*IN_F

typedef unsigned long long ull;

// ---------- device scratch (no allocations allowed) ----------
__device__ float  g_root[BATCH * NNODE * OUT_F];
__device__ float  g_Wl[IN_F * OUT_F];     // collapsed Wl1@Wl2, layout [f*3+o]
__device__ float  g_ceff[OUT_F * 6];      // collapsed c2w@c1w, layout [p*6+c]
__device__ float  g_beff[OUT_F];          // c2w@c1b + c2b
__device__ float4 g_x[BATCH * NPTS];      // (x0,x1,x2, 0.5*||x||^2)

// ---------- packed f32x2 helpers ----------
__device__ __forceinline__ ull splat2(float w) {
    ull r;
    asm("mov.b64 %0, {%1, %1};" : "=l"(r) : "f"(w));
    return r;
}
__device__ __forceinline__ void ffma2(ull& d, ull a, ull b) {
    asm("fma.rn.f32x2 %0, %1, %2, %0;" : "+l"(d) : "l"(a), "l"(b));
}
__device__ __forceinline__ ull ffma2r(ull a, ull b, ull c) {
    ull d;
    asm("fma.rn.f32x2 %0, %1, %2, %3;" : "=l"(d) : "l"(a), "l"(b), "l"(c));
    return d;
}
__device__ __forceinline__ ull add2r(ull a, ull b) {
    ull d;
    asm("add.rn.f32x2 %0, %1, %2;" : "=l"(d) : "l"(a), "l"(b));
    return d;
}
__device__ __forceinline__ float lo2(ull v) {
    return __uint_as_float((unsigned)(v & 0xffffffffu));
}
__device__ __forceinline__ float hi2(ull v) {
    return __uint_as_float((unsigned)(v >> 32));
}

__device__ __forceinline__ float wredsum(float v) {
    #pragma unroll
    for (int o = 16; o > 0; o >>= 1) v += __shfl_xor_sync(0xffffffffu, v, o);
    return v;
}

// ============================================================
// K0: parallel prep (unchanged — measured ~9.7us).
// ============================================================
__global__ __launch_bounds__(128) void k0_prep(
        const float* __restrict__ t0, const float* __restrict__ t1,
        const float* __restrict__ t2, const float* __restrict__ t3,
        const float* __restrict__ t4, const float* __restrict__ t5,
        const float* __restrict__ Wr0, const float* __restrict__ Wr1,
        const float* __restrict__ Wr2, const float* __restrict__ Wr3,
        const float* __restrict__ Wr4, const float* __restrict__ Wr5,
        const float* __restrict__ Wl1, const float* __restrict__ Wl2,
        const float* __restrict__ c1w, const float* __restrict__ c1b,
        const float* __restrict__ c2w, const float* __restrict__ c2b) {
    const int bid = blockIdx.x;
    const int tid = threadIdx.x;
    const int w   = tid >> 5, lane = tid & 31;
    __shared__ float red[4][3];

    if (bid < 512) {
        const int b = bid >> 5, n = bid & 31;
        float s0 = 0.f, s1 = 0.f, s2 = 0.f;
        for (int idx = tid; idx < 1120; idx += 128) {
            float v; const float* wp;
            if (idx < 96) {
                v = t0[b * 96 + idx];                           wp = Wr0 + idx * 3;
            } else if (idx < 352) {
                int i = idx - 96;
                v = t1[(b * 2  + (n >> 4)) * 256 + i];          wp = Wr1 + i * 3;
            } else if (idx < 608) {
                int i = idx - 352;
                v = t2[(b * 4  + (n >> 3)) * 256 + i];          wp = Wr2 + i * 3;
            } else if (idx < 864) {
                int i = idx - 608;
                v = t3[(b * 8  + (n >> 2)) * 256 + i];          wp = Wr3 + i * 3;
            } else if (idx < 992) {
                int i = idx - 864;
                v = t4[(b * 16 + (n >> 1)) * 128 + i];          wp = Wr4 + i * 3;
            } else {
                int i = idx - 992;
                v = t5[(b * 32 +  n      ) * 128 + i];          wp = Wr5 + i * 3;
            }
            s0 = fmaf(v, wp[0], s0); s1 = fmaf(v, wp[1], s1); s2 = fmaf(v, wp[2], s2);
        }
        s0 = wredsum(s0); s1 = wredsum(s1); s2 = wredsum(s2);
        if (lane == 0) { red[w][0] = s0; red[w][1] = s1; red[w][2] = s2; }
        __syncthreads();
        if (tid < 3)
            g_root[(b * NNODE + n) * 3 + tid] =
                red[0][tid] + red[1][tid] + red[2][tid] + red[3][tid];
    } else if (bid < 640) {
        const int f = bid - 512;
        float s0 = 0.f, s1 = 0.f, s2 = 0.f;
        for (int tt = tid; tt < 1280; tt += 128) {
            float v = Wl1[f * 1280 + tt];
            s0 = fmaf(v, Wl2[tt * 3 + 0], s0);
            s1 = fmaf(v, Wl2[tt * 3 + 1], s1);
            s2 = fmaf(v, Wl2[tt * 3 + 2], s2);
        }
        s0 = wredsum(s0); s1 = wredsum(s1); s2 = wredsum(s2);
        if (lane == 0) { red[w][0] = s0; red[w][1] = s1; red[w][2] = s2; }
        __syncthreads();
        if (tid < 3)
            g_Wl[f * 3 + tid] =
                red[0][tid] + red[1][tid] + red[2][tid] + red[3][tid];
    } else {
        if (tid < 18) {
            int p = tid / 6, c = tid % 6;
            float s = 0.f;
            for (int o = 0; o < 64; o++) s = fmaf(c2w[p * 64 + o], c1w[o * 6 + c], s);
            g_ceff[tid] = s;
        } else if (tid < 21) {
            int p = tid - 18;
            float s = c2b[p];
            for (int o = 0; o < 64; o++) s = fmaf(c2w[p * 64 + o], c1b[o], s);
            g_beff[p] = s;
        }
    }
}

// ============================================================
// K1: as R7 + __ldcs streaming loads for W_branch (134MB, zero reuse).
// ============================================================
__global__ __launch_bounds__(256) void k1_branch(const float* __restrict__ t5,
                                                 const float* __restrict__ Wb) {
    const int n   = blockIdx.x >> 4;
    const int jt  = blockIdx.x & 15;
    const int j0  = jt * 512;
    const int tid = threadIdx.x;

    __shared__ __align__(16) ull sa[IN_F * 8];  // [i][bpair]
    __shared__ __align__(8) float sC[16][516];
    __shared__ float sWl[IN_F * OUT_F];

    {
        int i = tid & 127, ph = (tid >> 7) * 4;
        #pragma unroll
        for (int pp = 0; pp < 4; pp++) {
            int p = ph + pp;
            float a0 = t5[((2 * p)     * NNODE + n) * IN_F + i];
            float a1 = t5[((2 * p + 1) * NNODE + n) * IN_F + i];
            sa[i * 8 + p] = ((ull)__float_as_uint(a1) << 32)
                          | (ull)__float_as_uint(a0);
        }
        for (int q = tid; q < IN_F * OUT_F; q += 256) sWl[q] = g_Wl[q];
    }
    __syncthreads();

    ull acc[2][8];
    #pragma unroll
    for (int c = 0; c < 2; c++)
        #pragma unroll
        for (int p = 0; p < 8; p++) acc[c][p] = 0ull;

    const float2* wptr =
        (const float2*)(Wb + (size_t)n * IN_F * JCOLS + j0 + 2 * tid);

    #pragma unroll 8
    for (int i = 0; i < IN_F; i++) {
        float2 w = __ldcs(wptr + (size_t)i * (JCOLS / 2));   // evict-first stream
        ull w0 = splat2(w.x), w1 = splat2(w.y);
        const ulonglong2* sap = (const ulonglong2*)(sa + i * 8);
        #pragma unroll
        for (int q = 0; q < 4; q++) {
            ulonglong2 ap = sap[q];
            ffma2(acc[0][2 * q],     ap.x, w0);
            ffma2(acc[1][2 * q],     ap.x, w1);
            ffma2(acc[0][2 * q + 1], ap.y, w0);
            ffma2(acc[1][2 * q + 1], ap.y, w1);
        }
    }

    #pragma unroll
    for (int p = 0; p < 8; p++) {
        float l0 = lo2(acc[0][p]), h0 = hi2(acc[0][p]);
        float l1 = lo2(acc[1][p]), h1 = hi2(acc[1][p]);
        l0 = l0 >= 0.f ? l0 : 0.2f * l0;
        h0 = h0 >= 0.f ? h0 : 0.2f * h0;
        l1 = l1 >= 0.f ? l1 : 0.2f * l1;
        h1 = h1 >= 0.f ? h1 : 0.2f * h1;
        *(float2*)&sC[2 * p][2 * tid]     = make_float2(l0, l1);
        *(float2*)&sC[2 * p + 1][2 * tid] = make_float2(h0, h1);
    }
    __syncthreads();

    if (tid < 64) {
        int d = tid >> 4, b = tid & 15;
        float s0 = 0.f, s1 = 0.f, s2 = 0.f;
        const float* row = &sC[b][d * 128];
        #pragma unroll 4
        for (int f = 0; f < 128; f++) {
            float cv = row[f];
            s0 = fmaf(cv, sWl[f * 3 + 0], s0);
            s1 = fmaf(cv, sWl[f * 3 + 1], s1);
            s2 = fmaf(cv, sWl[f * 3 + 2], s2);
        }
        const float* rp = &g_root[(b * NNODE + n) * 3];
        float x0 = s0 + rp[0], x1 = s1 + rp[1], x2 = s2 + rp[2];
        float hxx = 0.5f * (x0 * x0 + x1 * x1 + x2 * x2);
        int dglob = jt * 4 + d;
        g_x[b * NPTS + n * DEG + dglob] = make_float4(x0, x1, x2, hxx);
    }
}

// ============================================================
// K2: locality-ordered scan. Block == node: scan starts at the block's
// own node's 64 branches (points cluster tightly by node since
// |branchMLP| << |root|), so thresholds are ~final after 64 cands and
// the group prefilter skips ~all remaining groups. Inserts are
// tie-aware on (val desc, idx asc) == lax.top_k selection, making the
// selected SET independent of scan order (correctness guaranteed even
// if the locality hypothesis fails).
// ============================================================
__device__ __forceinline__ void topk_ins(float v, int m, float* val, int* idx) {
    float cv = v; int ci = m;
    #pragma unroll
    for (int s = 0; s < KNN; s++) {
        bool gt = (cv > val[s]) || (cv == val[s] && ci < idx[s]);
        float ov = val[s]; int oi = idx[s];
        val[s] = gt ? cv : ov;
        idx[s] = gt ? ci : oi;
        cv = gt ? ov : cv;
        ci = gt ? oi : ci;
    }
}

__global__ __launch_bounds__(64) void k2_knn(const float* __restrict__ bias,
                                             float* __restrict__ out) {
    const int b    = blockIdx.x >> 5;    // 16 batches x 32 nodes (chunks of 64)
    const int chnk = blockIdx.x & 31;
    const int tid  = threadIdx.x;

    __shared__ __align__(16) float sX[NPTS], sY[NPTS], sZ[NPTS], sW[NPTS];
    __shared__ float sce[18], sbe[3];
    #pragma unroll
    for (int q = 0; q < NPTS / 64; q++) {
        int i = q * 64 + tid;
        float4 v = g_x[b * NPTS + i];
        sX[i] = v.x; sY[i] = v.y; sZ[i] = v.z; sW[i] = -v.w;
    }
    if (tid < 18) sce[tid] = g_ceff[tid];
    if (tid < 3)  sbe[tid] = g_beff[tid];
    __syncthreads();

    const int n = chnk * 64 + tid;       // this thread's point
    const float nx = sX[n], ny = sY[n], nz = sZ[n];
    const ull nx2 = splat2(nx), ny2 = splat2(ny), nz2 = splat2(nz);
    const ull c0  = splat2(sW[n]);       // = -0.5*||xn||^2

    float val[KNN]; int idx[KNN];
    #pragma unroll
    for (int k = 0; k < KNN; k++) { val[k] = -3.4e38f; idx[k] = 0; }

    const ulonglong2* pX = (const ulonglong2*)sX;   // 512 entries (4 cands each)
    const ulonglong2* pY = (const ulonglong2*)sY;
    const ulonglong2* pZ = (const ulonglong2*)sZ;
    const ulonglong2* pW = (const ulonglong2*)sW;

    const int g0 = chnk * 8;             // own node's groups first (rotation)
    int gg = g0;
    ulonglong2 AX = pX[2 * gg],     AY = pY[2 * gg],
               AZ = pZ[2 * gg],     AW = pW[2 * gg];
    ulonglong2 BX = pX[2 * gg + 1], BY = pY[2 * gg + 1],
               BZ = pZ[2 * gg + 1], BW = pW[2 * gg + 1];

    #pragma unroll 1
    for (int t = 0; t < NPTS / 8; t++) {
        const int m0 = gg * 8;           // candidate base of current group
        ulonglong2 cX = AX, cY = AY, cZ = AZ, cW = AW;
        ulonglong2 dX = BX, dY = BY, dZ = BZ, dW = BW;
        int gn = (gg + 1) & 255;         // prefetch next (rotated) group
        if (t < NPTS / 8 - 1) {
            AX = pX[2 * gn];     AY = pY[2 * gn];
            AZ = pZ[2 * gn];     AW = pW[2 * gn];
            BX = pX[2 * gn + 1]; BY = pY[2 * gn + 1];
            BZ = pZ[2 * gn + 1]; BW = pW[2 * gn + 1];
        }
        gg = gn;
        ull t0 = ffma2r(nx2, cX.x, ffma2r(ny2, cY.x, ffma2r(nz2, cZ.x, add2r(c0, cW.x))));
        ull t1 = ffma2r(nx2, cX.y, ffma2r(ny2, cY.y, ffma2r(nz2, cZ.y, add2r(c0, cW.y))));
        ull t2 = ffma2r(nx2, dX.x, ffma2r(ny2, dY.x, ffma2r(nz2, dZ.x, add2r(c0, dW.x))));
        ull t3 = ffma2r(nx2, dX.y, ffma2r(ny2, dY.y, ffma2r(nz2, dZ.y, add2r(c0, dW.y))));
        float s0 = lo2(t0), s1 = hi2(t0), s2 = lo2(t1), s3 = hi2(t1);
        float s4 = lo2(t2), s5 = hi2(t2), s6 = lo2(t3), s7 = hi2(t3);
        float gm = fmaxf(fmaxf(fmaxf(s0, s1), fmaxf(s2, s3)),
                         fmaxf(fmaxf(s4, s5), fmaxf(s6, s7)));
        if (gm >= val[KNN - 1]) {        // >= : never miss boundary ties
            if (s0 >= val[KNN - 1]) topk_ins(s0, m0 + 0, val, idx);
            if (s1 >= val[KNN - 1]) topk_ins(s1, m0 + 1, val, idx);
            if (s2 >= val[KNN - 1]) topk_ins(s2, m0 + 2, val, idx);
            if (s3 >= val[KNN - 1]) topk_ins(s3, m0 + 3, val, idx);
            if (s4 >= val[KNN - 1]) topk_ins(s4, m0 + 4, val, idx);
            if (s5 >= val[KNN - 1]) topk_ins(s5, m0 + 5, val, idx);
            if (s6 >= val[KNN - 1]) topk_ins(s6, m0 + 6, val, idx);
            if (s7 >= val[KNN - 1]) topk_ins(s7, m0 + 7, val, idx);
        }
    }

    float h0 = -3.4e38f, h1 = -3.4e38f, h2 = -3.4e38f;
    #pragma unroll
    for (int k = 0; k < KNN; k++) {
        int m = idx[k];
        float mx = sX[m], my = sY[m], mz = sZ[m];
        float g0f = mx - nx, g1f = my - ny, g2f = mz - nz;
        float u0 = sbe[0] + sce[0]  * g0f + sce[1]  * g1f + sce[2]  * g2f
                          + sce[3]  * nx + sce[4]  * ny + sce[5]  * nz;
        float u1 = sbe[1] + sce[6]  * g0f + sce[7]  * g1f + sce[8]  * g2f
                          + sce[9]  * nx + sce[10] * ny + sce[11] * nz;
        float u2 = sbe[2] + sce[12] * g0f + sce[13] * g1f + sce[14] * g2f
                          + sce[15] * nx + sce[16] * ny + sce[17] * nz;
        h0 = fmaxf(h0, u0); h1 = fmaxf(h1, u1); h2 = fmaxf(h2, u2);
    }

    const int bq = tid * 3;              // bias tiled with period DEG=64; n&63==tid
    float o0 = h0 + bias[bq + 0];
    float o1 = h1 + bias[bq + 1];
    float o2 = h2 + bias[bq + 2];
    o0 = o0 >= 0.f ? o0 : 0.2f * o0;
    o1 = o1 >= 0.f ? o1 : 0.2f * o1;
    o2 = o2 >= 0.f ? o2 : 0.2f * o2;

    float* op = out + (size_t)(b * NPTS + n) * 3;
    op[0] = o0; op[1] = o1; op[2] = o2;
}

// ============================================================
extern "C" void kernel_launch(void* const* d_in, const int* in_sizes, int n_in,
                              void* d_out, int out_size) {
    const float* t0  = (const float*)d_in[0];
    const float* t1  = (const float*)d_in[1];
    const float* t2  = (const float*)d_in[2];
    const float* t3  = (const float*)d_in[3];
    const float* t4  = (const float*)d_in[4];
    const float* t5  = (const float*)d_in[5];
    const float* Wr0 = (const float*)d_in[6];
    const float* Wr1 = (const float*)d_in[7];
    const float* Wr2 = (const float*)d_in[8];
    const float* Wr3 = (const float*)d_in[9];
    const float* Wr4 = (const float*)d_in[10];
    const float* Wr5 = (const float*)d_in[11];
    const float* Wb  = (const float*)d_in[12];
    const float* Wl1 = (const float*)d_in[13];
    const float* Wl2 = (const float*)d_in[14];
    const float* bia = (const float*)d_in[15];
    const float* c1w = (const float*)d_in[16];
    const float* c1b = (const float*)d_in[17];
    const float* c2w = (const float*)d_in[18];
    const float* c2b = (const float*)d_in[19];

    k0_prep<<<641, 128>>>(t0, t1, t2, t3, t4, t5,
                          Wr0, Wr1, Wr2, Wr3, Wr4, Wr5,
                          Wl1, Wl2, c1w, c1b, c2w, c2b);
    k1_branch<<<NNODE * 16, 256>>>(t5, Wb);
    k2_knn<<<BATCH * 32, 64>>>(bia, (float*)d_out);
}